// round 13
// baseline (speedup 1.0000x reference)
#include <cuda_runtime.h>
#include <cuda_bf16.h>
#include <cstdint>

// Problem constants (fixed by reference)
constexpr int Bsz = 8, Ssz = 2048, Hn = 16, Dd = 64, SC = 512;
constexpr int BHn = Bsz * Hn;    // 128
constexpr int DM  = Hn * Dd;     // 1024
constexpr int Mrows = Bsz * Ssz; // 16384

// Scratch (device globals are the sanctioned no-alloc workaround)
__device__ __nv_bfloat16 g_Khi[BHn * SC * Dd];   // 8 MB  [bh][kv][64]
__device__ __nv_bfloat16 g_Klo[BHn * SC * Dd];   // 8 MB
__device__ __nv_bfloat16 g_Vhi[BHn * SC * Dd];   // 8 MB  [bh][64][kv]  (transposed)
__device__ __nv_bfloat16 g_Vlo[BHn * SC * Dd];   // 8 MB
__device__ __nv_bfloat16 g_Ahi[(size_t)Mrows * DM];  // 33.5 MB attn out hi
__device__ __nv_bfloat16 g_Alo[(size_t)Mrows * DM];  // 33.5 MB attn out lo
__device__ __nv_bfloat16 g_Bhi[DM * DM];         // 2 MB  W^T hi  [N,K]
__device__ __nv_bfloat16 g_Blo[DM * DM];         // 2 MB  W^T lo  [N,K]
__device__ __nv_bfloat16 g_CBhi[2][4][64 * 64];  // conv kernels, transposed [dout][din]
__device__ __nv_bfloat16 g_CBlo[2][4][64 * 64];

__device__ __forceinline__ uint32_t smem_u32(const void* p) {
    uint32_t a;
    asm("{ .reg .u64 t; cvta.to.shared.u64 t, %1; cvt.u32.u64 %0, t; }"
        : "=r"(a) : "l"(p));
    return a;
}

#define CP_ASYNC16(dst, src) \
    asm volatile("cp.async.cg.shared.global [%0], [%1], 16;" :: "r"(dst), "l"(src))
#define CP_COMMIT() asm volatile("cp.async.commit_group;" ::: "memory")
#define CP_WAIT(n)  asm volatile("cp.async.wait_group %0;" :: "n"(n) : "memory")

#define LDMATRIX_X4(r0, r1, r2, r3, addr) \
    asm volatile("ldmatrix.sync.aligned.m8n8.x4.shared.b16 {%0,%1,%2,%3}, [%4];" \
                 : "=r"(r0), "=r"(r1), "=r"(r2), "=r"(r3) : "r"(addr))

#define MMA_BF16(c, a, b) \
    asm volatile("mma.sync.aligned.m16n8k16.row.col.f32.bf16.bf16.f32 " \
                 "{%0,%1,%2,%3}, {%4,%5,%6,%7}, {%8,%9}, {%0,%1,%2,%3};" \
                 : "+f"((c)[0]), "+f"((c)[1]), "+f"((c)[2]), "+f"((c)[3]) \
                 : "r"((a)[0]), "r"((a)[1]), "r"((a)[2]), "r"((a)[3]), \
                   "r"((b)[0]), "r"((b)[1]))

#define MMA_BF16R(c, a, b0v, b1v) \
    asm volatile("mma.sync.aligned.m16n8k16.row.col.f32.bf16.bf16.f32 " \
                 "{%0,%1,%2,%3}, {%4,%5,%6,%7}, {%8,%9}, {%0,%1,%2,%3};" \
                 : "+f"((c)[0]), "+f"((c)[1]), "+f"((c)[2]), "+f"((c)[3]) \
                 : "r"((a)[0]), "r"((a)[1]), "r"((a)[2]), "r"((a)[3]), \
                   "r"(b0v), "r"(b1v))

__device__ __forceinline__ uint32_t sw128(uint32_t bo) {
    return bo ^ ((bo >> 3) & 0x70);
}

__device__ __forceinline__ float ex2f(float x) {
    float y;
    asm("ex2.approx.ftz.f32 %0, %1;" : "=f"(y) : "f"(x));
    return y;
}

// Split a pair of fp32 into packed bf16x2 hi + residual lo
__device__ __forceinline__ void split2(float a, float b, uint32_t& hi, uint32_t& lo) {
    __nv_bfloat162 th = __floats2bfloat162_rn(a, b);
    hi = *reinterpret_cast<uint32_t*>(&th);
    __nv_bfloat162 tl = __floats2bfloat162_rn(a - __low2float(th), b - __high2float(th));
    lo = *reinterpret_cast<uint32_t*>(&tl);
}

// ---------------------------------------------------------------------------
// prep_convB: kern[w][din][dout] f32 -> g_CB{hi,lo}[sel][w][dout][din] bf16
// ---------------------------------------------------------------------------
__global__ __launch_bounds__(256) void prep_convB(
    const float* __restrict__ kck, const float* __restrict__ vck)
{
    __shared__ float t[64][65];
    const int w = blockIdx.x, sel = blockIdx.y;
    const float* kern = (sel ? vck : kck) + w * 4096;
    const int tid = threadIdx.x;
#pragma unroll
    for (int i = 0; i < 16; ++i) {
        int idx = i * 256 + tid;
        t[idx >> 6][idx & 63] = kern[idx]; // [din][dout]
    }
    __syncthreads();
#pragma unroll
    for (int i = 0; i < 16; ++i) {
        int idx = i * 256 + tid;
        int dout = idx >> 6, din = idx & 63;
        float f = t[din][dout];
        __nv_bfloat16 hh = __float2bfloat16_rn(f);
        g_CBhi[sel][w][dout * 64 + din] = hh;
        g_CBlo[sel][w][dout * 64 + din] = __float2bfloat16_rn(f - __bfloat162float(hh));
    }
}

// ---------------------------------------------------------------------------
// compress_mma (exact 581.6-best form, two launches)
// ---------------------------------------------------------------------------
constexpr int CB_BS = 32768;      // B region: 4w x (hi 8K + lo 8K) = 64K
constexpr int CB_STG = 32768;     // staging overlays B after MMAs
constexpr int CMP_SMEM = 98304;   // A 32K + B 64K

__global__ __launch_bounds__(256, 2) void compress_mma(
    const float* __restrict__ x, const float* __restrict__ bias, int sel)
{
    extern __shared__ char smc[];
    const uint32_t sb = smem_u32(smc);
    const int tid = threadIdx.x, wid = tid >> 5, lane = tid & 31;
    const int bh = blockIdx.y, b = bh >> 4, h = bh & 15;
    const int t0 = blockIdx.x * 128;
    const int g8 = lane >> 3, r8 = lane & 7;
    const int a_row = (g8 & 1) * 8 + r8, a_kb = (g8 >> 1) * 16;
    const int b_row = (g8 >> 1) * 8 + r8, b_kb = (g8 & 1) * 16;

    {
        const __nv_bfloat16* hi = &g_CBhi[sel][0][0];
        const __nv_bfloat16* lo = &g_CBlo[sel][0][0];
#pragma unroll
        for (int i = 0; i < 16; ++i) {
            int idx = i * 256 + tid;
            int m = idx >> 9, rem = idx & 511;
            int w = m >> 1, hl = m & 1;
            int row = rem >> 3, seg = rem & 7;
            const __nv_bfloat16* g = hl ? lo : hi;
            const void* src = g + w * 4096 + row * 64 + seg * 8;
            uint32_t dst = sb + CB_BS + w * 16384 + hl * 8192 + sw128(row * 128 + seg * 16);
            CP_ASYNC16(dst, src);
        }
        CP_COMMIT();
    }

    const float* xb = x + ((size_t)b * Ssz * Hn + h) * Dd;

    float c[8][4];
#pragma unroll
    for (int i = 0; i < 8; ++i)
#pragma unroll
        for (int j = 0; j < 4; ++j) c[i][j] = 0.f;

    for (int w = 0; w < 4; ++w) {
        __syncthreads();
#pragma unroll
        for (int i = 0; i < 8; ++i) {
            int idx = i * 256 + tid, row = idx >> 4, c4 = idx & 15;
            float4 v = *(const float4*)(xb + (size_t)(4 * (t0 + row) + w) * DM + c4 * 4);
            uint32_t h0, l0, h1, l1;
            split2(v.x, v.y, h0, l0);
            split2(v.z, v.w, h1, l1);
            uint32_t off = sw128(row * 128 + c4 * 8);
            *(uint2*)(smc + off) = make_uint2(h0, h1);
            *(uint2*)(smc + 16384 + off) = make_uint2(l0, l1);
        }
        if (w == 0) CP_WAIT(0);
        __syncthreads();

        const uint32_t Ah = sb, Al = sb + 16384;
        const uint32_t Bh = sb + CB_BS + w * 16384, Bl = Bh + 8192;
        const int wqm = wid * 16;
#pragma unroll
        for (int kt = 0; kt < 4; ++kt) {
            uint32_t ah[4], al[4];
            uint32_t off = sw128((wqm + a_row) * 128 + kt * 32 + a_kb);
            LDMATRIX_X4(ah[0], ah[1], ah[2], ah[3], Ah + off);
            LDMATRIX_X4(al[0], al[1], al[2], al[3], Al + off);
#pragma unroll
            for (int np = 0; np < 4; ++np) {
                uint32_t boff = sw128((np * 16 + b_row) * 128 + kt * 32 + b_kb);
                uint32_t bh0, bh1, bh2, bh3, bl0, bl1, bl2, bl3;
                LDMATRIX_X4(bh0, bh1, bh2, bh3, Bh + boff);
                LDMATRIX_X4(bl0, bl1, bl2, bl3, Bl + boff);
                MMA_BF16R(c[np * 2], ah, bh0, bh1);
                MMA_BF16R(c[np * 2], ah, bl0, bl1);
                MMA_BF16R(c[np * 2], al, bh0, bh1);
                MMA_BF16R(c[np * 2 + 1], ah, bh2, bh3);
                MMA_BF16R(c[np * 2 + 1], ah, bl2, bl3);
                MMA_BF16R(c[np * 2 + 1], al, bh2, bh3);
            }
        }
    }

    __syncthreads();
    float* stg = (float*)(smc + CB_STG);
    const int cr = lane >> 2, cc2 = (lane & 3) * 2;
#pragma unroll
    for (int ni = 0; ni < 8; ++ni) {
        int col = ni * 8 + cc2;
        int row = wid * 16 + cr;
        float b0 = bias[col], b1 = bias[col + 1];
        stg[row * 68 + col] = c[ni][0] + b0;
        stg[row * 68 + col + 1] = c[ni][1] + b1;
        stg[(row + 8) * 68 + col] = c[ni][2] + b0;
        stg[(row + 8) * 68 + col + 1] = c[ni][3] + b1;
    }
    __syncthreads();

    if (sel == 0) {
        __nv_bfloat16* oh = g_Khi + ((size_t)bh * SC + t0) * Dd;
        __nv_bfloat16* ol = g_Klo + ((size_t)bh * SC + t0) * Dd;
#pragma unroll
        for (int i = 0; i < 8; ++i) {
            int idx = i * 256 + tid, row = idx >> 4, c4 = idx & 15;
            const float* p = stg + row * 68 + c4 * 4;
            uint32_t h0, l0, h1, l1;
            split2(p[0], p[1], h0, l0);
            split2(p[2], p[3], h1, l1);
            *(uint2*)(oh + row * 64 + c4 * 4) = make_uint2(h0, h1);
            *(uint2*)(ol + row * 64 + c4 * 4) = make_uint2(l0, l1);
        }
    } else {
        const int d = tid >> 2, tq = (tid & 3) * 32;
        union { __nv_bfloat16 e[32]; uint4 q[4]; } uh, ul;
#pragma unroll
        for (int j = 0; j < 32; ++j) {
            float v = stg[(tq + j) * 68 + d];
            __nv_bfloat16 hh = __float2bfloat16_rn(v);
            uh.e[j] = hh;
            ul.e[j] = __float2bfloat16_rn(v - __bfloat162float(hh));
        }
        __nv_bfloat16* oh = g_Vhi + ((size_t)bh * Dd + d) * SC + t0 + tq;
        __nv_bfloat16* ol = g_Vlo + ((size_t)bh * Dd + d) * SC + t0 + tq;
#pragma unroll
        for (int j = 0; j < 4; ++j) {
            *(uint4*)(oh + j * 8) = uh.q[j];
            *(uint4*)(ol + j * 8) = ul.q[j];
        }
    }
}

// ---------------------------------------------------------------------------
// Attention v3: 32 q-rows per warp (two m-tiles), 256 q-rows per CTA.
// Every K/V fragment feeds 12 MMAs (was 6). kv-chunks of 64, triple-buffered
// 32KB stages; Q (64KB) overlays stage slots 1+2, extracted before overwrite.
// Per-accumulator K-order unchanged -> bit-identical numerics.
// ---------------------------------------------------------------------------
constexpr int AST = 32768;                 // stage: Khi|Klo|Vhi|Vlo 8K each
constexpr int ATTN_SMEM = 3 * AST;         // 98304

__global__ __launch_bounds__(256, 1) void attn_mma(const float* __restrict__ q)
{
    extern __shared__ char smc[];
    const uint32_t sb = smem_u32(smc);
    const int tid = threadIdx.x, wid = tid >> 5, lane = tid & 31;
    const int bh = blockIdx.y, b = bh >> 4, h = bh & 15;
    const int s0 = blockIdx.x * 256;
    const int g8 = lane >> 3, r8 = lane & 7;
    const float qscale = 0.125f * 1.4426950408889634f; // 1/sqrt(64) * log2(e)
    const uint32_t QOFF = AST;              // Q hi: slots 1 region start (32KB)
    const uint32_t QLO  = 2 * AST;          // Q lo: slot 2 region (32KB)

    // stage 0 prefetch can start immediately (slot 0, disjoint from Q区)
    auto load_stage = [&](int s, int ch) {
        const uint32_t stg = sb + s * AST;
#pragma unroll
        for (int i = 0; i < 8; ++i) {
            int idx = i * 256 + tid;
            int mat = idx >> 9, rem = idx & 511;
            int row = rem >> 3, seg = rem & 7;
            const void* src;
            if (mat < 2) {
                const __nv_bfloat16* g = mat ? g_Klo : g_Khi;
                src = g + ((size_t)bh * SC + ch * 64 + row) * Dd + seg * 8;
            } else {
                const __nv_bfloat16* g = (mat == 3) ? g_Vlo : g_Vhi;
                src = g + ((size_t)bh * Dd + row) * SC + ch * 64 + seg * 8;
            }
            uint32_t dst = stg + mat * 8192 + sw128(row * 128 + seg * 16);
            CP_ASYNC16(dst, src);
        }
        CP_COMMIT();
    };
    load_stage(0, 0);

    // ---- Q tile: 256 rows fp32 -> bf16 hi/lo, SW128-swizzled, slots 1+2 ----
    const float* qb = q + ((size_t)(b * Ssz + s0) * Hn + h) * Dd;
#pragma unroll
    for (int i = 0; i < 16; ++i) {
        int idx = i * 256 + tid, row = idx >> 4, c4 = idx & 15;
        float4 v = *(const float4*)(qb + (size_t)row * DM + c4 * 4);
        uint32_t h0, l0, h1, l1;
        split2(v.x * qscale, v.y * qscale, h0, l0);
        split2(v.z * qscale, v.w * qscale, h1, l1);
        uint32_t off = sw128(row * 128 + c4 * 8);
        *(uint2*)(smc + QOFF + off) = make_uint2(h0, h1);
        *(uint2*)(smc + QLO + off) = make_uint2(l0, l1);
    }
    __syncthreads(); // Q visible

    // ---- extract Q fragments for both m-tiles (register-resident) ----
    const int wqm = wid * 32;
    const int a_row = (g8 & 1) * 8 + r8, a_kb = (g8 >> 1) * 16;
    const int b_row = (g8 >> 1) * 8 + r8, b_kb = (g8 & 1) * 16;
    uint32_t qh[2][4][4], ql[2][4][4];
#pragma unroll
    for (int mt = 0; mt < 2; ++mt)
#pragma unroll
        for (int kt = 0; kt < 4; ++kt) {
            uint32_t off = sw128((wqm + mt * 16 + a_row) * 128 + kt * 32 + a_kb);
            LDMATRIX_X4(qh[mt][kt][0], qh[mt][kt][1], qh[mt][kt][2], qh[mt][kt][3],
                        sb + QOFF + off);
            LDMATRIX_X4(ql[mt][kt][0], ql[mt][kt][1], ql[mt][kt][2], ql[mt][kt][3],
                        sb + QLO + off);
        }
    __syncthreads(); // all warps done reading Q before slots 1/2 reused
    load_stage(1, 1);

    float o[16][4];
#pragma unroll
    for (int nd = 0; nd < 16; ++nd)
#pragma unroll
        for (int j = 0; j < 4; ++j) o[nd][j] = 0.f;
    float la0 = 0.f, la1 = 0.f, lb0 = 0.f, lb1 = 0.f;

    for (int ch = 0; ch < 8; ++ch) {
        CP_WAIT(1);          // own groups: stage ch landed
        __syncthreads();     // publish + WAR fence
        if (ch + 2 < 8) load_stage((ch + 2) % 3, ch + 2);
        else CP_COMMIT();

        const uint32_t Kh = sb + (ch % 3) * AST;
        const uint32_t Kl = Kh + 8192, Vh = Kh + 16384, Vl = Kh + 24576;

        // ---- S = Q*K^T (32q x 64kv), 3-term; K frags shared by both m-tiles
        float s[16][4];
#pragma unroll
        for (int j = 0; j < 16; ++j)
#pragma unroll
            for (int e = 0; e < 4; ++e) s[j][e] = 0.f;
#pragma unroll
        for (int kt = 0; kt < 4; ++kt)
#pragma unroll
            for (int p = 0; p < 4; ++p) {
                uint32_t kh0, kh1, kh2, kh3, kl0, kl1, kl2, kl3;
                uint32_t off = sw128((p * 16 + b_row) * 128 + kt * 32 + b_kb);
                LDMATRIX_X4(kh0, kh1, kh2, kh3, Kh + off);
                LDMATRIX_X4(kl0, kl1, kl2, kl3, Kl + off);
#pragma unroll
                for (int mt = 0; mt < 2; ++mt) {
                    float* s0p = s[mt * 8 + 2 * p];
                    float* s1p = s[mt * 8 + 2 * p + 1];
                    MMA_BF16R(s0p, qh[mt][kt], kh0, kh1);
                    MMA_BF16R(s0p, qh[mt][kt], kl0, kl1);
                    MMA_BF16R(s0p, ql[mt][kt], kh0, kh1);
                    MMA_BF16R(s1p, qh[mt][kt], kh2, kh3);
                    MMA_BF16R(s1p, qh[mt][kt], kl2, kl3);
                    MMA_BF16R(s1p, ql[mt][kt], kh2, kh3);
                }
            }

        // ---- PV with ex2/split folded per kt; V frags shared by m-tiles ----
#pragma unroll
        for (int kt = 0; kt < 4; ++kt) {
            uint32_t ahi[2][4], alo[2][4];
#pragma unroll
            for (int mt = 0; mt < 2; ++mt) {
                float* sa = s[mt * 8 + 2 * kt];
                float* sc = s[mt * 8 + 2 * kt + 1];
                sa[0] = ex2f(sa[0]); sa[1] = ex2f(sa[1]);
                sa[2] = ex2f(sa[2]); sa[3] = ex2f(sa[3]);
                sc[0] = ex2f(sc[0]); sc[1] = ex2f(sc[1]);
                sc[2] = ex2f(sc[2]); sc[3] = ex2f(sc[3]);
                if (mt == 0) {
                    la0 += sa[0] + sa[1] + sc[0] + sc[1];
                    la1 += sa[2] + sa[3] + sc[2] + sc[3];
                } else {
                    lb0 += sa[0] + sa[1] + sc[0] + sc[1];
                    lb1 += sa[2] + sa[3] + sc[2] + sc[3];
                }
                split2(sa[0], sa[1], ahi[mt][0], alo[mt][0]);
                split2(sa[2], sa[3], ahi[mt][1], alo[mt][1]);
                split2(sc[0], sc[1], ahi[mt][2], alo[mt][2]);
                split2(sc[2], sc[3], ahi[mt][3], alo[mt][3]);
            }
#pragma unroll
            for (int nd2 = 0; nd2 < 4; ++nd2) {
                uint32_t off = sw128((nd2 * 16 + b_row) * 128 + kt * 32 + b_kb);
                uint32_t vh0, vh1, vh2, vh3, vl0, vl1, vl2, vl3;
                LDMATRIX_X4(vh0, vh1, vh2, vh3, Vh + off);
                LDMATRIX_X4(vl0, vl1, vl2, vl3, Vl + off);
#pragma unroll
                for (int mt = 0; mt < 2; ++mt) {
                    float* o0p = o[mt * 8 + nd2 * 2];
                    float* o1p = o[mt * 8 + nd2 * 2 + 1];
                    MMA_BF16R(o0p, ahi[mt], vh0, vh1);
                    MMA_BF16R(o0p, ahi[mt], vl0, vl1);
                    MMA_BF16R(o0p, alo[mt], vh0, vh1);
                    MMA_BF16R(o1p, ahi[mt], vh2, vh3);
                    MMA_BF16R(o1p, ahi[mt], vl2, vl3);
                    MMA_BF16R(o1p, alo[mt], vh2, vh3);
                }
            }
        }
    }

    // ---- deferred l reductions across the lane quad ----
    la0 += __shfl_xor_sync(0xffffffffu, la0, 1);
    la0 += __shfl_xor_sync(0xffffffffu, la0, 2);
    la1 += __shfl_xor_sync(0xffffffffu, la1, 1);
    la1 += __shfl_xor_sync(0xffffffffu, la1, 2);
    lb0 += __shfl_xor_sync(0xffffffffu, lb0, 1);
    lb0 += __shfl_xor_sync(0xffffffffu, lb0, 2);
    lb1 += __shfl_xor_sync(0xffffffffu, lb1, 1);
    lb1 += __shfl_xor_sync(0xffffffffu, lb1, 2);

    // ---- epilogue: normalize, emit bf16 hi/lo in [B,S,DM] layout ----
    const int r = lane >> 2, cb = (lane & 3) * 2;
#pragma unroll
    for (int mt = 0; mt < 2; ++mt) {
        const float inv0 = 1.0f / (mt ? lb0 : la0);
        const float inv1 = 1.0f / (mt ? lb1 : la1);
        const size_t row0 = (size_t)b * Ssz + s0 + wqm + mt * 16 + r;
        __nv_bfloat16* baseH = g_Ahi + row0 * DM + h * Dd + cb;
        __nv_bfloat16* baseL = g_Alo + row0 * DM + h * Dd + cb;
#pragma unroll
        for (int nd = 0; nd < 8; ++nd) {
            uint32_t hh, ll;
            split2(o[mt * 8 + nd][0] * inv0, o[mt * 8 + nd][1] * inv0, hh, ll);
            *(uint32_t*)(baseH + nd * 8) = hh;
            *(uint32_t*)(baseL + nd * 8) = ll;
            split2(o[mt * 8 + nd][2] * inv1, o[mt * 8 + nd][3] * inv1, hh, ll);
            *(uint32_t*)(baseH + 8 * DM + nd * 8) = hh;
            *(uint32_t*)(baseL + 8 * DM + nd * 8) = ll;
        }
    }
}

// ---------------------------------------------------------------------------
// W prep: transpose + bf16 hi/lo split.  W[K,N] f32 -> Bt[N,K] bf16 (hi, lo)
// ---------------------------------------------------------------------------
__global__ __launch_bounds__(256) void prepW_kernel(const float* __restrict__ W)
{
    __shared__ float t[32][33];
    const int nb = blockIdx.x * 32, kb = blockIdx.y * 32;
    const int c = threadIdx.x & 31, r0 = threadIdx.x >> 5;
#pragma unroll
    for (int i = 0; i < 4; ++i) {
        int r = r0 + i * 8;
        t[r][c] = W[(size_t)(kb + r) * DM + nb + c];
    }
    __syncthreads();
#pragma unroll
    for (int i = 0; i < 4; ++i) {
        int r = r0 + i * 8;
        float f = t[c][r];
        __nv_bfloat16 hh = __float2bfloat16_rn(f);
        size_t o = (size_t)(nb + r) * DM + kb + c;
        g_Bhi[o] = hh;
        g_Blo[o] = __float2bfloat16_rn(f - __bfloat162float(hh));
    }
}

// ---------------------------------------------------------------------------
// Projection via mma.sync (exact 581.6-best form: BK=64, double buffer).
// ---------------------------------------------------------------------------
constexpr int BM = 128, BN = 128, BK = 64, NCH = DM / BK; // 16 chunks
constexpr int MAT = BM * BK * 2;          // 16 KB per matrix (bf16)
constexpr int STAGE = 4 * MAT;            // Ahi|Alo|Bhi|Blo = 64 KB
constexpr int PROJ_SMEM = 2 * STAGE;      // 128 KB

__global__ __launch_bounds__(256, 1) void proj_mma(float* __restrict__ C)
{
    extern __shared__ char smc[];
    const uint32_t sb = smem_u32(smc);
    const int tid = threadIdx.x, wid = tid >> 5, lane = tid & 31;
    const int m0 = blockIdx.y * BM, n0 = blockIdx.x * BN;
    const int wm = (wid & 1) * 64, wn = (wid >> 1) * 32;

    auto load_stage = [&](int s, int ch) {
        const int k0 = ch * BK;
        const uint32_t stg = sb + s * STAGE;
#pragma unroll
        for (int i = 0; i < 16; ++i) {
            int idx = i * 256 + tid;
            int mat = idx >> 10, rem = idx & 1023;
            int row = rem >> 3, seg = rem & 7;
            const __nv_bfloat16* g;
            int gr;
            if (mat == 0)      { g = g_Ahi; gr = m0 + row; }
            else if (mat == 1) { g = g_Alo; gr = m0 + row; }
            else if (mat == 2) { g = g_Bhi; gr = n0 + row; }
            else               { g = g_Blo; gr = n0 + row; }
            const void* src = g + (size_t)gr * DM + k0 + seg * 8;
            uint32_t dst = stg + mat * MAT + sw128(row * 128 + seg * 16);
            CP_ASYNC16(dst, src);
        }
        CP_COMMIT();
    };

    float c[16][4];
#pragma unroll
    for (int i = 0; i < 16; ++i)
#pragma unroll
        for (int j = 0; j < 4; ++j) c[i][j] = 0.f;

    const int g8 = lane >> 3, r8 = lane & 7;
    const int a_row = (g8 & 1) * 8 + r8;
    const int a_kb  = (g8 >> 1) * 16;
    const int b_row = (g8 >> 1) * 8 + r8;
    const int b_kb  = (g8 & 1) * 16;

    load_stage(0, 0);
    load_stage(1, 1);

    for (int ch = 0; ch < NCH; ++ch) {
        CP_WAIT(1);
        __syncthreads();
        const uint32_t stg = sb + (ch & 1) * STAGE;
        const uint32_t Ah = stg, Al = stg + MAT, Bh = stg + 2 * MAT, Bl = stg + 3 * MAT;
#pragma unroll
        for (int k16 = 0; k16 < BK / 16; ++k16) {
            const int kb = k16 * 32;
            uint32_t ah[4][4], al[4][4], bh[4][2], bl[4][2];
#pragma unroll
            for (int mi = 0; mi < 4; ++mi) {
                uint32_t off = sw128((wm + mi * 16 + a_row) * 128 + kb + a_kb);
                LDMATRIX_X4(ah[mi][0], ah[mi][1], ah[mi][2], ah[mi][3], Ah + off);
                LDMATRIX_X4(al[mi][0], al[mi][1], al[mi][2], al[mi][3], Al + off);
            }
#pragma unroll
            for (int np = 0; np < 2; ++np) {
                uint32_t off = sw128((wn + np * 16 + b_row) * 128 + kb + b_kb);
                uint32_t t0, t1, t2, t3;
                LDMATRIX_X4(t0, t1, t2, t3, Bh + off);
                bh[np * 2][0] = t0; bh[np * 2][1] = t1;
                bh[np * 2 + 1][0] = t2; bh[np * 2 + 1][1] = t3;
                LDMATRIX_X4(t0, t1, t2, t3, Bl + off);
                bl[np * 2][0] = t0; bl[np * 2][1] = t1;
                bl[np * 2 + 1][0] = t2; bl[np * 2 + 1][1] = t3;
            }
#pragma unroll
            for (int mi = 0; mi < 4; ++mi)
#pragma unroll
                for (int ni = 0; ni < 4; ++ni) {
                    float* cc = c[mi * 4 + ni];
                    MMA_BF16(cc, ah[mi], bh[ni]);
                    MMA_BF16(cc, ah[mi], bl[ni]);
                    MMA_BF16(cc, al[mi], bh[ni]);
                }
        }
        __syncthreads();
        if (ch + 2 < NCH) load_stage(ch & 1, ch + 2);
        else CP_COMMIT();
    }

    const int cr = lane >> 2, cc2 = (lane & 3) * 2;
#pragma unroll
    for (int mi = 0; mi < 4; ++mi)
#pragma unroll
        for (int ni = 0; ni < 4; ++ni) {
            float* cp0 = C + (size_t)(m0 + wm + mi * 16 + cr) * DM + n0 + wn + ni * 8 + cc2;
            float* cp1 = cp0 + 8 * DM;
            const float* f = c[mi * 4 + ni];
            *(float2*)cp0 = make_float2(f[0], f[1]);
            *(float2*)cp1 = make_float2(f[2], f[3]);
        }
}

// ---------------------------------------------------------------------------
extern "C" void kernel_launch(void* const* d_in, const int* in_sizes, int n_in,
                              void* d_out, int out_size)
{
    const float* pre_q = (const float*)d_in[0];
    const float* pre_k = (const float*)d_in[1];
    const float* pre_v = (const float*)d_in[2];
    const float* kck   = (const float*)d_in[3];
    const float* kcb   = (const float*)d_in[4];
    const float* vck   = (const float*)d_in[5];
    const float* vcb   = (const float*)d_in[6];
    const float* Wm    = (const float*)d_in[7];
    float* out = (float*)d_out;

    cudaFuncSetAttribute(compress_mma, cudaFuncAttributeMaxDynamicSharedMemorySize, CMP_SMEM);
    cudaFuncSetAttribute(attn_mma, cudaFuncAttributeMaxDynamicSharedMemorySize, ATTN_SMEM);
    cudaFuncSetAttribute(proj_mma, cudaFuncAttributeMaxDynamicSharedMemorySize, PROJ_SMEM);

    prep_convB<<<dim3(4, 2), 256>>>(kck, vck);
    prepW_kernel<<<dim3(32, 32), 256>>>(Wm);
    compress_mma<<<dim3(4, 128), 256, CMP_SMEM>>>(pre_k, kcb, 0);
    compress_mma<<<dim3(4, 128), 256, CMP_SMEM>>>(pre_v, vcb, 1);
    attn_mma<<<dim3(8, 128), 256, ATTN_SMEM>>>(pre_q);
    proj_mma<<<dim3(DM / BN, Mrows / BM), 256, PROJ_SMEM>>>(out);
}

// round 14
// speedup vs baseline: 1.0176x; 1.0176x over previous
#include <cuda_runtime.h>
#include <cuda_bf16.h>
#include <cstdint>

// Problem constants (fixed by reference)
constexpr int Bsz = 8, Ssz = 2048, Hn = 16, Dd = 64, SC = 512;
constexpr int BHn = Bsz * Hn;    // 128
constexpr int DM  = Hn * Dd;     // 1024
constexpr int Mrows = Bsz * Ssz; // 16384

// Scratch (device globals are the sanctioned no-alloc workaround)
__device__ __nv_bfloat16 g_Khi[BHn * SC * Dd];   // 8 MB  [bh][kv][64]
__device__ __nv_bfloat16 g_Klo[BHn * SC * Dd];   // 8 MB
__device__ __nv_bfloat16 g_Vhi[BHn * SC * Dd];   // 8 MB  [bh][64][kv]  (transposed)
__device__ __nv_bfloat16 g_Vlo[BHn * SC * Dd];   // 8 MB
__device__ __nv_bfloat16 g_Ahi[(size_t)Mrows * DM];  // 33.5 MB attn out hi
__device__ __nv_bfloat16 g_Alo[(size_t)Mrows * DM];  // 33.5 MB attn out lo
__device__ __nv_bfloat16 g_Bhi[DM * DM];         // 2 MB  W^T hi  [N,K]
__device__ __nv_bfloat16 g_Blo[DM * DM];         // 2 MB  W^T lo  [N,K]
__device__ __nv_bfloat16 g_CBhi[2][4][64 * 64];  // conv kernels, transposed [dout][din]
__device__ __nv_bfloat16 g_CBlo[2][4][64 * 64];

__device__ __forceinline__ uint32_t smem_u32(const void* p) {
    uint32_t a;
    asm("{ .reg .u64 t; cvta.to.shared.u64 t, %1; cvt.u32.u64 %0, t; }"
        : "=r"(a) : "l"(p));
    return a;
}

#define CP_ASYNC16(dst, src) \
    asm volatile("cp.async.cg.shared.global [%0], [%1], 16;" :: "r"(dst), "l"(src))
#define CP_COMMIT() asm volatile("cp.async.commit_group;" ::: "memory")
#define CP_WAIT(n)  asm volatile("cp.async.wait_group %0;" :: "n"(n) : "memory")

#define LDMATRIX_X4(r0, r1, r2, r3, addr) \
    asm volatile("ldmatrix.sync.aligned.m8n8.x4.shared.b16 {%0,%1,%2,%3}, [%4];" \
                 : "=r"(r0), "=r"(r1), "=r"(r2), "=r"(r3) : "r"(addr))

#define MMA_BF16(c, a, b) \
    asm volatile("mma.sync.aligned.m16n8k16.row.col.f32.bf16.bf16.f32 " \
                 "{%0,%1,%2,%3}, {%4,%5,%6,%7}, {%8,%9}, {%0,%1,%2,%3};" \
                 : "+f"((c)[0]), "+f"((c)[1]), "+f"((c)[2]), "+f"((c)[3]) \
                 : "r"((a)[0]), "r"((a)[1]), "r"((a)[2]), "r"((a)[3]), \
                   "r"((b)[0]), "r"((b)[1]))

#define MMA_BF16R(c, a, b0v, b1v) \
    asm volatile("mma.sync.aligned.m16n8k16.row.col.f32.bf16.bf16.f32 " \
                 "{%0,%1,%2,%3}, {%4,%5,%6,%7}, {%8,%9}, {%0,%1,%2,%3};" \
                 : "+f"((c)[0]), "+f"((c)[1]), "+f"((c)[2]), "+f"((c)[3]) \
                 : "r"((a)[0]), "r"((a)[1]), "r"((a)[2]), "r"((a)[3]), \
                   "r"(b0v), "r"(b1v))

__device__ __forceinline__ uint32_t sw128(uint32_t bo) {
    return bo ^ ((bo >> 3) & 0x70);
}

__device__ __forceinline__ float ex2f(float x) {
    float y;
    asm("ex2.approx.ftz.f32 %0, %1;" : "=f"(y) : "f"(x));
    return y;
}

// Split a pair of fp32 into packed bf16x2 hi + residual lo
__device__ __forceinline__ void split2(float a, float b, uint32_t& hi, uint32_t& lo) {
    __nv_bfloat162 th = __floats2bfloat162_rn(a, b);
    hi = *reinterpret_cast<uint32_t*>(&th);
    __nv_bfloat162 tl = __floats2bfloat162_rn(a - __low2float(th), b - __high2float(th));
    lo = *reinterpret_cast<uint32_t*>(&tl);
}

// ---------------------------------------------------------------------------
// prep_all: blockIdx.x < 1024 -> W transpose+split tile; else conv kernel tile.
// ---------------------------------------------------------------------------
__global__ __launch_bounds__(256) void prep_all(
    const float* __restrict__ W,
    const float* __restrict__ kck, const float* __restrict__ vck)
{
    __shared__ float t[64][65];
    const int bid = blockIdx.x, tid = threadIdx.x;
    if (bid < 1024) {
        // W[K,N] f32 -> g_B{hi,lo}[N,K] bf16
        const int nb = (bid & 31) * 32, kb = (bid >> 5) * 32;
        const int c = tid & 31, r0 = tid >> 5;
#pragma unroll
        for (int i = 0; i < 4; ++i) {
            int r = r0 + i * 8;
            t[r][c] = W[(size_t)(kb + r) * DM + nb + c];
        }
        __syncthreads();
#pragma unroll
        for (int i = 0; i < 4; ++i) {
            int r = r0 + i * 8;
            float f = t[c][r];
            __nv_bfloat16 hh = __float2bfloat16_rn(f);
            size_t o = (size_t)(nb + r) * DM + kb + c;
            g_Bhi[o] = hh;
            g_Blo[o] = __float2bfloat16_rn(f - __bfloat162float(hh));
        }
    } else {
        const int idx4 = bid - 1024;
        const int w = idx4 & 3, sel = idx4 >> 2;
        const float* kern = (sel ? vck : kck) + w * 4096;
#pragma unroll
        for (int i = 0; i < 16; ++i) {
            int idx = i * 256 + tid;
            t[idx >> 6][idx & 63] = kern[idx]; // [din][dout]
        }
        __syncthreads();
#pragma unroll
        for (int i = 0; i < 16; ++i) {
            int idx = i * 256 + tid;
            int dout = idx >> 6, din = idx & 63;
            float f = t[din][dout];
            __nv_bfloat16 hh = __float2bfloat16_rn(f);
            g_CBhi[sel][w][dout * 64 + din] = hh;
            g_CBlo[sel][w][dout * 64 + din] = __float2bfloat16_rn(f - __bfloat162float(hh));
        }
    }
}

// ---------------------------------------------------------------------------
// compress_mma (exact 581.6-best form, two launches)
// ---------------------------------------------------------------------------
constexpr int CB_BS = 32768;      // B region: 4w x (hi 8K + lo 8K) = 64K
constexpr int CB_STG = 32768;     // staging overlays B after MMAs
constexpr int CMP_SMEM = 98304;   // A 32K + B 64K

__global__ __launch_bounds__(256, 2) void compress_mma(
    const float* __restrict__ x, const float* __restrict__ bias, int sel)
{
    extern __shared__ char smc[];
    const uint32_t sb = smem_u32(smc);
    const int tid = threadIdx.x, wid = tid >> 5, lane = tid & 31;
    const int bh = blockIdx.y, b = bh >> 4, h = bh & 15;
    const int t0 = blockIdx.x * 128;
    const int g8 = lane >> 3, r8 = lane & 7;
    const int a_row = (g8 & 1) * 8 + r8, a_kb = (g8 >> 1) * 16;
    const int b_row = (g8 >> 1) * 8 + r8, b_kb = (g8 & 1) * 16;

    {
        const __nv_bfloat16* hi = &g_CBhi[sel][0][0];
        const __nv_bfloat16* lo = &g_CBlo[sel][0][0];
#pragma unroll
        for (int i = 0; i < 16; ++i) {
            int idx = i * 256 + tid;
            int m = idx >> 9, rem = idx & 511;
            int w = m >> 1, hl = m & 1;
            int row = rem >> 3, seg = rem & 7;
            const __nv_bfloat16* g = hl ? lo : hi;
            const void* src = g + w * 4096 + row * 64 + seg * 8;
            uint32_t dst = sb + CB_BS + w * 16384 + hl * 8192 + sw128(row * 128 + seg * 16);
            CP_ASYNC16(dst, src);
        }
        CP_COMMIT();
    }

    const float* xb = x + ((size_t)b * Ssz * Hn + h) * Dd;

    float c[8][4];
#pragma unroll
    for (int i = 0; i < 8; ++i)
#pragma unroll
        for (int j = 0; j < 4; ++j) c[i][j] = 0.f;

    for (int w = 0; w < 4; ++w) {
        __syncthreads();
#pragma unroll
        for (int i = 0; i < 8; ++i) {
            int idx = i * 256 + tid, row = idx >> 4, c4 = idx & 15;
            float4 v = *(const float4*)(xb + (size_t)(4 * (t0 + row) + w) * DM + c4 * 4);
            uint32_t h0, l0, h1, l1;
            split2(v.x, v.y, h0, l0);
            split2(v.z, v.w, h1, l1);
            uint32_t off = sw128(row * 128 + c4 * 8);
            *(uint2*)(smc + off) = make_uint2(h0, h1);
            *(uint2*)(smc + 16384 + off) = make_uint2(l0, l1);
        }
        if (w == 0) CP_WAIT(0);
        __syncthreads();

        const uint32_t Ah = sb, Al = sb + 16384;
        const uint32_t Bh = sb + CB_BS + w * 16384, Bl = Bh + 8192;
        const int wqm = wid * 16;
#pragma unroll
        for (int kt = 0; kt < 4; ++kt) {
            uint32_t ah[4], al[4];
            uint32_t off = sw128((wqm + a_row) * 128 + kt * 32 + a_kb);
            LDMATRIX_X4(ah[0], ah[1], ah[2], ah[3], Ah + off);
            LDMATRIX_X4(al[0], al[1], al[2], al[3], Al + off);
#pragma unroll
            for (int np = 0; np < 4; ++np) {
                uint32_t boff = sw128((np * 16 + b_row) * 128 + kt * 32 + b_kb);
                uint32_t bh0, bh1, bh2, bh3, bl0, bl1, bl2, bl3;
                LDMATRIX_X4(bh0, bh1, bh2, bh3, Bh + boff);
                LDMATRIX_X4(bl0, bl1, bl2, bl3, Bl + boff);
                MMA_BF16R(c[np * 2], ah, bh0, bh1);
                MMA_BF16R(c[np * 2], ah, bl0, bl1);
                MMA_BF16R(c[np * 2], al, bh0, bh1);
                MMA_BF16R(c[np * 2 + 1], ah, bh2, bh3);
                MMA_BF16R(c[np * 2 + 1], ah, bl2, bl3);
                MMA_BF16R(c[np * 2 + 1], al, bh2, bh3);
            }
        }
    }

    __syncthreads();
    float* stg = (float*)(smc + CB_STG);
    const int cr = lane >> 2, cc2 = (lane & 3) * 2;
#pragma unroll
    for (int ni = 0; ni < 8; ++ni) {
        int col = ni * 8 + cc2;
        int row = wid * 16 + cr;
        float b0 = bias[col], b1 = bias[col + 1];
        stg[row * 68 + col] = c[ni][0] + b0;
        stg[row * 68 + col + 1] = c[ni][1] + b1;
        stg[(row + 8) * 68 + col] = c[ni][2] + b0;
        stg[(row + 8) * 68 + col + 1] = c[ni][3] + b1;
    }
    __syncthreads();

    if (sel == 0) {
        __nv_bfloat16* oh = g_Khi + ((size_t)bh * SC + t0) * Dd;
        __nv_bfloat16* ol = g_Klo + ((size_t)bh * SC + t0) * Dd;
#pragma unroll
        for (int i = 0; i < 8; ++i) {
            int idx = i * 256 + tid, row = idx >> 4, c4 = idx & 15;
            const float* p = stg + row * 68 + c4 * 4;
            uint32_t h0, l0, h1, l1;
            split2(p[0], p[1], h0, l0);
            split2(p[2], p[3], h1, l1);
            *(uint2*)(oh + row * 64 + c4 * 4) = make_uint2(h0, h1);
            *(uint2*)(ol + row * 64 + c4 * 4) = make_uint2(l0, l1);
        }
    } else {
        const int d = tid >> 2, tq = (tid & 3) * 32;
        union { __nv_bfloat16 e[32]; uint4 q[4]; } uh, ul;
#pragma unroll
        for (int j = 0; j < 32; ++j) {
            float v = stg[(tq + j) * 68 + d];
            __nv_bfloat16 hh = __float2bfloat16_rn(v);
            uh.e[j] = hh;
            ul.e[j] = __float2bfloat16_rn(v - __bfloat162float(hh));
        }
        __nv_bfloat16* oh = g_Vhi + ((size_t)bh * Dd + d) * SC + t0 + tq;
        __nv_bfloat16* ol = g_Vlo + ((size_t)bh * Dd + d) * SC + t0 + tq;
#pragma unroll
        for (int j = 0; j < 4; ++j) {
            *(uint4*)(oh + j * 8) = uh.q[j];
            *(uint4*)(ol + j * 8) = ul.q[j];
        }
    }
}

// ---------------------------------------------------------------------------
// Attention (exact 581.6-best form: kv-chunks of 64, triple-buffered 32KB
// stages, Q overlays slot 2, 2 CTAs/SM)
// ---------------------------------------------------------------------------
constexpr int AST = 32768;                 // stage: Khi|Klo|Vhi|Vlo 8K each
constexpr int ATTN_SMEM = 3 * AST;         // 98304; 2 CTAs/SM

__global__ __launch_bounds__(256, 2) void attn_mma(const float* __restrict__ q)
{
    extern __shared__ char smc[];
    const uint32_t sb = smem_u32(smc);
    const int tid = threadIdx.x, wid = tid >> 5, lane = tid & 31;
    const int bh = blockIdx.y, b = bh >> 4, h = bh & 15;
    const int s0 = blockIdx.x * 128;
    const int g8 = lane >> 3, r8 = lane & 7;
    const float qscale = 0.125f * 1.4426950408889634f; // 1/sqrt(64) * log2(e)
    const uint32_t QOFF = 2 * AST;          // Q staged in slot 2 region (32KB)

    const float* qb = q + ((size_t)(b * Ssz + s0) * Hn + h) * Dd;
#pragma unroll
    for (int i = 0; i < 8; ++i) {
        int idx = i * 256 + tid, row = idx >> 4, c4 = idx & 15;
        float4 v = *(const float4*)(qb + (size_t)row * DM + c4 * 4);
        uint32_t h0, l0, h1, l1;
        split2(v.x * qscale, v.y * qscale, h0, l0);
        split2(v.z * qscale, v.w * qscale, h1, l1);
        uint32_t off = sw128(row * 128 + c4 * 8);
        *(uint2*)(smc + QOFF + off) = make_uint2(h0, h1);
        *(uint2*)(smc + QOFF + 16384 + off) = make_uint2(l0, l1);
    }

    auto load_stage = [&](int s, int ch) {
        const uint32_t stg = sb + s * AST;
#pragma unroll
        for (int i = 0; i < 8; ++i) {
            int idx = i * 256 + tid;
            int mat = idx >> 9, rem = idx & 511;
            int row = rem >> 3, seg = rem & 7;
            const void* src;
            if (mat < 2) {
                const __nv_bfloat16* g = mat ? g_Klo : g_Khi;
                src = g + ((size_t)bh * SC + ch * 64 + row) * Dd + seg * 8;
            } else {
                const __nv_bfloat16* g = (mat == 3) ? g_Vlo : g_Vhi;
                src = g + ((size_t)bh * Dd + row) * SC + ch * 64 + seg * 8;
            }
            uint32_t dst = stg + mat * 8192 + sw128(row * 128 + seg * 16);
            CP_ASYNC16(dst, src);
        }
        CP_COMMIT();
    };

    load_stage(0, 0);
    load_stage(1, 1);
    __syncthreads(); // Q visible to all warps

    const int wqm = wid * 16;
    const int a_row = (g8 & 1) * 8 + r8, a_kb = (g8 >> 1) * 16;
    const int b_row = (g8 >> 1) * 8 + r8, b_kb = (g8 & 1) * 16;
    uint32_t qh[4][4], ql[4][4];
#pragma unroll
    for (int kt = 0; kt < 4; ++kt) {
        uint32_t off = sw128((wqm + a_row) * 128 + kt * 32 + a_kb);
        LDMATRIX_X4(qh[kt][0], qh[kt][1], qh[kt][2], qh[kt][3], sb + QOFF + off);
        LDMATRIX_X4(ql[kt][0], ql[kt][1], ql[kt][2], ql[kt][3], sb + QOFF + 16384 + off);
    }

    float o[8][4];
#pragma unroll
    for (int nd = 0; nd < 8; ++nd)
#pragma unroll
        for (int j = 0; j < 4; ++j) o[nd][j] = 0.f;
    float l0 = 0.f, l1 = 0.f;

    for (int ch = 0; ch < 8; ++ch) {
        CP_WAIT(1);
        __syncthreads();
        if (ch + 2 < 8) load_stage((ch + 2) % 3, ch + 2);
        else CP_COMMIT();

        const uint32_t Kh = sb + (ch % 3) * AST;
        const uint32_t Kl = Kh + 8192, Vh = Kh + 16384, Vl = Kh + 24576;

        float s[8][4];
#pragma unroll
        for (int j = 0; j < 8; ++j)
#pragma unroll
            for (int e = 0; e < 4; ++e) s[j][e] = 0.f;
#pragma unroll
        for (int kt = 0; kt < 4; ++kt)
#pragma unroll
            for (int p = 0; p < 4; ++p) {
                uint32_t kh0, kh1, kh2, kh3, kl0, kl1, kl2, kl3;
                uint32_t off = sw128((p * 16 + b_row) * 128 + kt * 32 + b_kb);
                LDMATRIX_X4(kh0, kh1, kh2, kh3, Kh + off);
                LDMATRIX_X4(kl0, kl1, kl2, kl3, Kl + off);
                MMA_BF16R(s[2 * p], qh[kt], kh0, kh1);
                MMA_BF16R(s[2 * p], qh[kt], kl0, kl1);
                MMA_BF16R(s[2 * p], ql[kt], kh0, kh1);
                MMA_BF16R(s[2 * p + 1], qh[kt], kh2, kh3);
                MMA_BF16R(s[2 * p + 1], qh[kt], kl2, kl3);
                MMA_BF16R(s[2 * p + 1], ql[kt], kh2, kh3);
            }

#pragma unroll
        for (int kt = 0; kt < 4; ++kt) {
            float* sa = s[2 * kt];
            float* sc = s[2 * kt + 1];
            sa[0] = ex2f(sa[0]); sa[1] = ex2f(sa[1]);
            sa[2] = ex2f(sa[2]); sa[3] = ex2f(sa[3]);
            sc[0] = ex2f(sc[0]); sc[1] = ex2f(sc[1]);
            sc[2] = ex2f(sc[2]); sc[3] = ex2f(sc[3]);
            l0 += sa[0] + sa[1] + sc[0] + sc[1];
            l1 += sa[2] + sa[3] + sc[2] + sc[3];
            uint32_t ahi[4], alo[4];
            split2(sa[0], sa[1], ahi[0], alo[0]);
            split2(sa[2], sa[3], ahi[1], alo[1]);
            split2(sc[0], sc[1], ahi[2], alo[2]);
            split2(sc[2], sc[3], ahi[3], alo[3]);
#pragma unroll
            for (int nd2 = 0; nd2 < 4; ++nd2) {
                uint32_t off = sw128((nd2 * 16 + b_row) * 128 + kt * 32 + b_kb);
                uint32_t vh0, vh1, vh2, vh3, vl0, vl1, vl2, vl3;
                LDMATRIX_X4(vh0, vh1, vh2, vh3, Vh + off);
                LDMATRIX_X4(vl0, vl1, vl2, vl3, Vl + off);
                MMA_BF16R(o[nd2 * 2], ahi, vh0, vh1);
                MMA_BF16R(o[nd2 * 2], ahi, vl0, vl1);
                MMA_BF16R(o[nd2 * 2], alo, vh0, vh1);
                MMA_BF16R(o[nd2 * 2 + 1], ahi, vh2, vh3);
                MMA_BF16R(o[nd2 * 2 + 1], ahi, vl2, vl3);
                MMA_BF16R(o[nd2 * 2 + 1], alo, vh2, vh3);
            }
        }
    }

    l0 += __shfl_xor_sync(0xffffffffu, l0, 1);
    l0 += __shfl_xor_sync(0xffffffffu, l0, 2);
    l1 += __shfl_xor_sync(0xffffffffu, l1, 1);
    l1 += __shfl_xor_sync(0xffffffffu, l1, 2);

    const float inv0 = 1.0f / l0, inv1 = 1.0f / l1;
    const int r = lane >> 2, cb = (lane & 3) * 2;
    const size_t row0 = (size_t)b * Ssz + s0 + wqm + r;
    __nv_bfloat16* baseH = g_Ahi + row0 * DM + h * Dd + cb;
    __nv_bfloat16* baseL = g_Alo + row0 * DM + h * Dd + cb;
#pragma unroll
    for (int nd = 0; nd < 8; ++nd) {
        uint32_t hh, ll;
        split2(o[nd][0] * inv0, o[nd][1] * inv0, hh, ll);
        *(uint32_t*)(baseH + nd * 8) = hh;
        *(uint32_t*)(baseL + nd * 8) = ll;
        split2(o[nd][2] * inv1, o[nd][3] * inv1, hh, ll);
        *(uint32_t*)(baseH + 8 * DM + nd * 8) = hh;
        *(uint32_t*)(baseL + 8 * DM + nd * 8) = ll;
    }
}

// ---------------------------------------------------------------------------
// Persistent projection: 148 CTAs, each walks tiles bid, bid+148, ... as one
// flat chunk stream; double-buffer prefetch crosses tile boundaries so the
// pipeline never drains. Inner loop identical to the 581.6-best proj.
// ---------------------------------------------------------------------------
constexpr int BM = 128, BN = 128, BK = 64, NCH = DM / BK; // 16 chunks
constexpr int NTILES = (Mrows / BM) * (DM / BN);          // 1024
constexpr int PGRID = 148;
constexpr int MAT = BM * BK * 2;          // 16 KB per matrix (bf16)
constexpr int STAGE = 4 * MAT;            // Ahi|Alo|Bhi|Blo = 64 KB
constexpr int PROJ_SMEM = 2 * STAGE;      // 128 KB

__global__ __launch_bounds__(256, 1) void proj_mma(float* __restrict__ C)
{
    extern __shared__ char smc[];
    const uint32_t sb = smem_u32(smc);
    const int tid = threadIdx.x, wid = tid >> 5, lane = tid & 31;
    const int bid = blockIdx.x;
    const int wm = (wid & 1) * 64, wn = (wid >> 1) * 32;

    const int nT = (bid < NTILES) ? ((NTILES - 1 - bid) / PGRID + 1) : 0;
    const int total = nT * NCH;
    if (total == 0) return;

    // tile of flat step s; tile t -> m0 = (t>>3)*128, n0 = (t&7)*128
    auto load_step = [&](int buf, int st) {
        const int t = bid + (st >> 4) * PGRID;
        const int m0 = (t >> 3) * BM, n0 = (t & 7) * BN;
        const int k0 = (st & 15) * BK;
        const uint32_t stg = sb + buf * STAGE;
#pragma unroll
        for (int i = 0; i < 16; ++i) {
            int idx = i * 256 + tid;
            int mat = idx >> 10, rem = idx & 1023;
            int row = rem >> 3, seg = rem & 7;
            const __nv_bfloat16* g;
            int gr;
            if (mat == 0)      { g = g_Ahi; gr = m0 + row; }
            else if (mat == 1) { g = g_Alo; gr = m0 + row; }
            else if (mat == 2) { g = g_Bhi; gr = n0 + row; }
            else               { g = g_Blo; gr = n0 + row; }
            const void* src = g + (size_t)gr * DM + k0 + seg * 8;
            uint32_t dst = stg + mat * MAT + sw128(row * 128 + seg * 16);
            CP_ASYNC16(dst, src);
        }
        CP_COMMIT();
    };

    float c[16][4];
#pragma unroll
    for (int i = 0; i < 16; ++i)
#pragma unroll
        for (int j = 0; j < 4; ++j) c[i][j] = 0.f;

    const int g8 = lane >> 3, r8 = lane & 7;
    const int a_row = (g8 & 1) * 8 + r8;
    const int a_kb  = (g8 >> 1) * 16;
    const int b_row = (g8 >> 1) * 8 + r8;
    const int b_kb  = (g8 & 1) * 16;
    const int cr = lane >> 2, cc2 = (lane & 3) * 2;

    load_step(0, 0);
    if (total > 1) load_step(1, 1);
    else CP_COMMIT();

    for (int st = 0; st < total; ++st) {
        CP_WAIT(1);
        __syncthreads();
        const uint32_t stg = sb + (st & 1) * STAGE;
        const uint32_t Ah = stg, Al = stg + MAT, Bh = stg + 2 * MAT, Bl = stg + 3 * MAT;
#pragma unroll
        for (int k16 = 0; k16 < BK / 16; ++k16) {
            const int kb = k16 * 32;
            uint32_t ah[4][4], al[4][4], bh[4][2], bl[4][2];
#pragma unroll
            for (int mi = 0; mi < 4; ++mi) {
                uint32_t off = sw128((wm + mi * 16 + a_row) * 128 + kb + a_kb);
                LDMATRIX_X4(ah[mi][0], ah[mi][1], ah[mi][2], ah[mi][3], Ah + off);
                LDMATRIX_X4(al[mi][0], al[mi][1], al[mi][2], al[mi][3], Al + off);
            }
#pragma unroll
            for (int np = 0; np < 2; ++np) {
                uint32_t off = sw128((wn + np * 16 + b_row) * 128 + kb + b_kb);
                uint32_t t0, t1, t2, t3;
                LDMATRIX_X4(t0, t1, t2, t3, Bh + off);
                bh[np * 2][0] = t0; bh[np * 2][1] = t1;
                bh[np * 2 + 1][0] = t2; bh[np * 2 + 1][1] = t3;
                LDMATRIX_X4(t0, t1, t2, t3, Bl + off);
                bl[np * 2][0] = t0; bl[np * 2][1] = t1;
                bl[np * 2 + 1][0] = t2; bl[np * 2 + 1][1] = t3;
            }
#pragma unroll
            for (int mi = 0; mi < 4; ++mi)
#pragma unroll
                for (int ni = 0; ni < 4; ++ni) {
                    float* cc = c[mi * 4 + ni];
                    MMA_BF16(cc, ah[mi], bh[ni]);
                    MMA_BF16(cc, ah[mi], bl[ni]);
                    MMA_BF16(cc, al[mi], bh[ni]);
                }
        }
        __syncthreads();
        if (st + 2 < total) load_step(st & 1, st + 2);
        else CP_COMMIT();

        if ((st & 15) == 15) {
            // epilogue for the tile just finished (registers -> gmem)
            const int t = bid + (st >> 4) * PGRID;
            const int m0 = (t >> 3) * BM, n0 = (t & 7) * BN;
#pragma unroll
            for (int mi = 0; mi < 4; ++mi)
#pragma unroll
                for (int ni = 0; ni < 4; ++ni) {
                    float* cp0 = C + (size_t)(m0 + wm + mi * 16 + cr) * DM
                               + n0 + wn + ni * 8 + cc2;
                    float* cp1 = cp0 + 8 * DM;
                    float* f = c[mi * 4 + ni];
                    *(float2*)cp0 = make_float2(f[0], f[1]);
                    *(float2*)cp1 = make_float2(f[2], f[3]);
                    f[0] = f[1] = f[2] = f[3] = 0.f;
                }
        }
    }
}

// ---------------------------------------------------------------------------
extern "C" void kernel_launch(void* const* d_in, const int* in_sizes, int n_in,
                              void* d_out, int out_size)
{
    const float* pre_q = (const float*)d_in[0];
    const float* pre_k = (const float*)d_in[1];
    const float* pre_v = (const float*)d_in[2];
    const float* kck   = (const float*)d_in[3];
    const float* kcb   = (const float*)d_in[4];
    const float* vck   = (const float*)d_in[5];
    const float* vcb   = (const float*)d_in[6];
    const float* Wm    = (const float*)d_in[7];
    float* out = (float*)d_out;

    cudaFuncSetAttribute(compress_mma, cudaFuncAttributeMaxDynamicSharedMemorySize, CMP_SMEM);
    cudaFuncSetAttribute(attn_mma, cudaFuncAttributeMaxDynamicSharedMemorySize, ATTN_SMEM);
    cudaFuncSetAttribute(proj_mma, cudaFuncAttributeMaxDynamicSharedMemorySize, PROJ_SMEM);

    prep_all<<<dim3(1032), 256>>>(Wm, kck, vck);
    compress_mma<<<dim3(4, 128), 256, CMP_SMEM>>>(pre_k, kcb, 0);
    compress_mma<<<dim3(4, 128), 256, CMP_SMEM>>>(pre_v, vcb, 1);
    attn_mma<<<dim3(16, 128), 256, ATTN_SMEM>>>(pre_q);
    proj_mma<<<dim3(PGRID), 256, PROJ_SMEM>>>(out);
}